// round 17
// baseline (speedup 1.0000x reference)
#include <cuda_runtime.h>
#include <cuda_bf16.h>
#include <math.h>
#include <stdint.h>

// ---------------- problem constants ----------------
constexpr int V_  = 32000;
constexpr int E_  = 256;
constexpr int H_  = 512;
constexpr int LAT_= 100;
constexpr int NL_ = 3;
constexpr int B_  = 128;
constexpr int S_  = 32;
constexpr int BH_ = B_ * H_;

constexpr int NTILE = V_ / 128;   // 250 vocab n-tiles of 128
constexpr int KC    = H_ / 32;    // 16 k-chunks of 32 (vocab GEMM)

// ---------------- persistent device state ----------------
__device__ float g_cbuf[NL_ * BH_];
__device__ int   g_tok[B_];
__device__ unsigned long long g_arg[B_];

// bf16 hi/lo splits.
// Vocab weights: [ntile][kc][n(128)][k(32)]
__device__ __align__(16) __nv_bfloat16 g_Whi[(size_t)V_ * H_];
__device__ __align__(16) __nv_bfloat16 g_Wlo[(size_t)V_ * H_];
// Cell weights (gate-interleaved rows j=h*4+g): [layer][ntile(32)][kc(32)][row(64)][k(32)]
constexpr size_t WC_L = (size_t)32 * 32 * 64 * 32;   // per-layer stride (2M elems)
__device__ __align__(16) __nv_bfloat16 g_Wc_hi[NL_ * WC_L];
__device__ __align__(16) __nv_bfloat16 g_Wc_lo[NL_ * WC_L];
// Hidden state, split form only, double buffered: [buf][layer][b*512+h]
__device__ __align__(16) __nv_bfloat16 g_hhi[2][NL_][BH_];
__device__ __align__(16) __nv_bfloat16 g_hlo[2][NL_][BH_];
// Layer-0 input (split embedding rows): [b][E]
__device__ __align__(16) __nv_bfloat16 g_x0hi[B_ * E_];
__device__ __align__(16) __nv_bfloat16 g_x0lo[B_ * E_];

__device__ __forceinline__ float sigf(float x) { return 1.0f / (1.0f + expf(-x)); }

__device__ __forceinline__ unsigned int fkey(float f) {
    unsigned int u = __float_as_uint(f);
    return (u & 0x80000000u) ? ~u : (u | 0x80000000u);
}

// ---------------- PTX helpers (baseline ISA, legal on plain sm_103) ----------------
__device__ __forceinline__ uint32_t smem_u32(const void* p) {
    uint32_t a;
    asm("{ .reg .u64 t; cvta.to.shared.u64 t, %1; cvt.u32.u64 %0, t; }" : "=r"(a) : "l"(p));
    return a;
}
__device__ __forceinline__ void ldsm4(uint32_t* r, uint32_t addr) {
    asm volatile("ldmatrix.sync.aligned.m8n8.x4.shared.b16 {%0,%1,%2,%3}, [%4];"
                 : "=r"(r[0]), "=r"(r[1]), "=r"(r[2]), "=r"(r[3]) : "r"(addr));
}
__device__ __forceinline__ void ldsm2(uint32_t* r, uint32_t addr) {
    asm volatile("ldmatrix.sync.aligned.m8n8.x2.shared.b16 {%0,%1}, [%2];"
                 : "=r"(r[0]), "=r"(r[1]) : "r"(addr));
}
__device__ __forceinline__ void mma16816(float* c, const uint32_t* a, const uint32_t* b) {
    asm volatile("mma.sync.aligned.m16n8k16.row.col.f32.bf16.bf16.f32 "
                 "{%0,%1,%2,%3}, {%4,%5,%6,%7}, {%8,%9}, {%0,%1,%2,%3};"
                 : "+f"(c[0]), "+f"(c[1]), "+f"(c[2]), "+f"(c[3])
                 : "r"(a[0]), "r"(a[1]), "r"(a[2]), "r"(a[3]), "r"(b[0]), "r"(b[1]));
}
#define CPA16(dst, src) asm volatile("cp.async.cg.shared.global [%0], [%1], 16;" :: "r"(dst), "l"(src))
#define CPA_COMMIT()    asm volatile("cp.async.commit_group;" ::: "memory")
#define CPA_WAIT(n)     asm volatile("cp.async.wait_group %0;" :: "n"(n) : "memory")

// ---------------- init: h0 = tanh(noise @ W_lat^T + b_lat), split to bf16 ----------------
__global__ void init_kernel(const float* __restrict__ noise,
                            const float* __restrict__ W_lat,
                            const float* __restrict__ b_lat) {
    int j = blockIdx.x * blockDim.x + threadIdx.x;
    if (j < NL_ * BH_) {
        int row = j / (NL_ * H_);
        int col = j % (NL_ * H_);
        const float* np = noise + row * LAT_;
        const float* wp = W_lat + (size_t)col * LAT_;
        float s = b_lat[col];
        #pragma unroll 4
        for (int k = 0; k < LAT_; k++) s = fmaf(np[k], wp[k], s);
        float h = tanhf(s);
        __nv_bfloat16 hv = __float2bfloat16(h);
        // flat (B, NL*H) == flat (NL, B, H): write buffer 1 ("prev" for t=0)
        ((__nv_bfloat16*)g_hhi)[NL_ * BH_ + j] = hv;
        ((__nv_bfloat16*)g_hlo)[NL_ * BH_ + j] = __float2bfloat16(h - __bfloat162float(hv));
        g_cbuf[j] = 0.0f;
    }
    if (j < B_) { g_tok[j] = 1; g_arg[j] = 0ULL; }
}

// ---------------- W_fc -> bf16 hi/lo tile images (vocab) ----------------
__global__ void convw_kernel(const float* __restrict__ W_fc) {
    int j = blockIdx.x * blockDim.x + threadIdx.x;
    if (j >= V_ * H_) return;
    int n = j >> 9;
    int k = j & 511;
    float w = W_fc[j];
    __nv_bfloat16 hv = __float2bfloat16(w);
    float lo = w - __bfloat162float(hv);
    int ntile = n >> 7, nloc = n & 127;
    int kc = k >> 5, kk = k & 31;
    size_t off = (((size_t)(ntile * KC + kc) * 128 + nloc) << 5) + kk;
    g_Whi[off] = hv;
    g_Wlo[off] = __float2bfloat16(lo);
}

// ---------------- cell weights -> gate-interleaved bf16 hi/lo tiles ----------------
// combo row j = h*4 + g  <- original row g*512 + h of [Wih | Whh] (K-concat)
__global__ void convcell_kernel(int layer, int K1,
                                const float* __restrict__ Wih,
                                const float* __restrict__ Whh) {
    int KT = K1 + H_;
    int j = blockIdx.x * blockDim.x + threadIdx.x;
    if (j >= 2048 * KT) return;
    int kk = j % KT;
    int cmb = j / KT;
    int h = cmb >> 2, g = cmb & 3;
    float w = (kk < K1) ? Wih[(size_t)(g * H_ + h) * K1 + kk]
                        : Whh[(size_t)(g * H_ + h) * H_ + (kk - K1)];
    __nv_bfloat16 hv = __float2bfloat16(w);
    float lo = w - __bfloat162float(hv);
    size_t off = ((size_t)layer * 32 + (cmb >> 6)) * (32 * 2048)
               + (size_t)(kk >> 5) * 2048 + (cmb & 63) * 32 + (kk & 31);
    g_Wc_hi[off] = hv;
    g_Wc_lo[off] = __float2bfloat16(lo);
}

// ---------------- HMMA LSTM cell: GEMM + fused gate epilogue ----------------
// Output tile: 64 batch x 64 gate-combos (=16 h x 4 gates). Grid (32 ntiles, 2 mtiles).
// 128 threads = 4 warps (warpN 0..3, warp tile 64x16). bf16 3-term split, fp32 acc.
// ALL state pointers resolved in DEVICE code from __device__ symbols (host-passed
// device-symbol pointers resolve to the host shadow via GB300 ATS -> silent zeros).
constexpr int CLDA = 40;
constexpr int CARR = 64 * CLDA * 2;   // 5120 B per array
constexpr int CSTG = 4 * CARR;        // 20480 per stage (Ahi,Alo,Bhi,Blo)
constexpr int CSM_TOTAL = 2 * CSTG;   // 40960 (epilogue stage reuses this region)

__global__ __launch_bounds__(128) void cell_mma(
    int cb, int pb, int layer, int K1,
    const float* __restrict__ bih, const float* __restrict__ bhh)
{
    extern __shared__ __align__(16) char dsm[];
    const uint32_t smb = smem_u32(dsm);
    const int tid = threadIdx.x;
    const int wid = tid >> 5, lane = tid & 31;
    const int ntile = blockIdx.x;        // 0..31 (combo tiles of 64)
    const int mtile = blockIdx.y;        // 0..1  (batch halves of 64)

    // device-side pointer resolution (the R16 bug fix)
    const __nv_bfloat16* xhi = (layer == 0) ? g_x0hi : g_hhi[cb][layer - 1];
    const __nv_bfloat16* xlo = (layer == 0) ? g_x0lo : g_hlo[cb][layer - 1];
    const __nv_bfloat16* hhi_p = g_hhi[pb][layer];
    const __nv_bfloat16* hlo_p = g_hlo[pb][layer];

    const int KCL = (K1 + H_) / 32;
    const size_t wbase = ((size_t)layer * 32 + ntile) * (32 * 2048);

    auto load_stage = [&](int stage, int kc) {
        const uint32_t sdst = smb + stage * CSTG;
        #pragma unroll
        for (int i = 0; i < 8; i++) {
            int c = tid + i * 128;          // 1024 chunks of 16B
            int arr = c >> 8, idx = c & 255;
            int row = idx >> 2, seg = idx & 3;
            uint32_t dst = sdst + arr * CARR + (uint32_t)(row * CLDA + seg * 8) * 2;
            int gk = kc * 32 + seg * 8;
            const __nv_bfloat16* src;
            if (arr < 2) {
                int b = mtile * 64 + row;
                src = (gk < K1) ? (arr == 0 ? xhi : xlo) + (size_t)b * K1 + gk
                                : (arr == 0 ? hhi_p : hlo_p) + (size_t)b * H_ + (gk - K1);
            } else {
                src = (arr == 2 ? g_Wc_hi : g_Wc_lo) + wbase + (size_t)kc * 2048 + row * 32 + seg * 8;
            }
            CPA16(dst, src);
        }
    };

    // ldmatrix lane addressing (same scheme as the proven vocab kernel)
    const int aRow = (lane & 7) + ((lane >> 3) & 1) * 8;
    const int aK   = ((lane >> 4) & 1) * 8;
    const uint32_t aBase = smb + (uint32_t)(aRow * CLDA + aK) * 2;
    const int bl   = lane & 15;
    const int bRow = wid * 16 + (bl & 7);
    const int bK   = ((bl >> 3) & 1) * 8;
    const uint32_t bBase = smb + 2 * CARR + (uint32_t)(bRow * CLDA + bK) * 2;

    float acc[4][2][4];
    #pragma unroll
    for (int mf = 0; mf < 4; mf++)
        #pragma unroll
        for (int nf = 0; nf < 2; nf++)
            #pragma unroll
            for (int i = 0; i < 4; i++) acc[mf][nf][i] = 0.0f;

    load_stage(0, 0);
    CPA_COMMIT();

    for (int kc = 0; kc < KCL; kc++) {
        if (kc + 1 < KCL) {
            load_stage((kc + 1) & 1, kc + 1);
            CPA_COMMIT();
            CPA_WAIT(1);
        } else {
            CPA_WAIT(0);
        }
        __syncthreads();

        const uint32_t soff = (kc & 1) * CSTG;
        #pragma unroll
        for (int k16 = 0; k16 < 2; k16++) {
            const uint32_t kb2 = (uint32_t)(k16 * 16) * 2;
            uint32_t bhi[2][2], blo[2][2];
            #pragma unroll
            for (int nf = 0; nf < 2; nf++) {
                uint32_t ba = bBase + soff + (uint32_t)(nf * 8 * CLDA) * 2 + kb2;
                ldsm2(bhi[nf], ba);
                ldsm2(blo[nf], ba + CARR);
            }
            uint32_t ahi[4][4], alo[4][4];
            #pragma unroll
            for (int mf = 0; mf < 4; mf++) {
                uint32_t aa = aBase + soff + (uint32_t)(mf * 16 * CLDA) * 2 + kb2;
                ldsm4(ahi[mf], aa);
                ldsm4(alo[mf], aa + CARR);
            }
            #pragma unroll
            for (int mf = 0; mf < 4; mf++)
                #pragma unroll
                for (int nf = 0; nf < 2; nf++) {
                    mma16816(acc[mf][nf], ahi[mf], bhi[nf]);
                    mma16816(acc[mf][nf], ahi[mf], blo[nf]);
                    mma16816(acc[mf][nf], alo[mf], bhi[nf]);
                }
        }
        __syncthreads();
    }

    // ---- fused LSTM epilogue ----
    float* st = (float*)dsm;   // [64][68] fp32 stage (reuses tile smem)
    #pragma unroll
    for (int mf = 0; mf < 4; mf++)
        #pragma unroll
        for (int nf = 0; nf < 2; nf++) {
            int row = mf * 16 + (lane >> 2);
            int col = wid * 16 + nf * 8 + 2 * (lane & 3);
            st[row * 68 + col]           = acc[mf][nf][0];
            st[row * 68 + col + 1]       = acc[mf][nf][1];
            st[(row + 8) * 68 + col]     = acc[mf][nf][2];
            st[(row + 8) * 68 + col + 1] = acc[mf][nf][3];
        }
    __syncthreads();

    const int h_local = tid & 15, bsub = tid >> 4;
    const int hglob = ntile * 16 + h_local;
    const float bi = bih[hglob]            + bhh[hglob];
    const float bf = bih[H_ + hglob]       + bhh[H_ + hglob];
    const float bg = bih[2 * H_ + hglob]   + bhh[2 * H_ + hglob];
    const float bo = bih[3 * H_ + hglob]   + bhh[3 * H_ + hglob];
    float* crow = &g_cbuf[layer * BH_];
    __nv_bfloat16* ohi = g_hhi[cb][layer];
    __nv_bfloat16* olo = g_hlo[cb][layer];
    #pragma unroll
    for (int r = 0; r < 8; r++) {
        const int blc = bsub * 8 + r;
        const int bglob = mtile * 64 + blc;
        float4 gt = *(const float4*)&st[blc * 68 + h_local * 4];
        float iv = sigf(gt.x + bi);
        float fv = sigf(gt.y + bf);
        float gv = tanhf(gt.z + bg);
        float ov = sigf(gt.w + bo);
        const int off = bglob * H_ + hglob;
        float c2 = fmaf(fv, crow[off], iv * gv);
        float h2 = ov * tanhf(c2);
        crow[off] = c2;
        __nv_bfloat16 hv = __float2bfloat16(h2);
        ohi[off] = hv;
        olo[off] = __float2bfloat16(h2 - __bfloat162float(hv));
    }
}

// ---------------- HMMA vocab GEMM + bias + logits + gumbel argmax ----------------
constexpr int LDA  = 40;
constexpr int ARRB = 128 * LDA * 2;         // 10240 B per array
constexpr int STG  = 4 * ARRB;              // 40960 per stage
constexpr int SM_BEST = 2 * STG;            // u64[128]
constexpr int SM_TOTAL = SM_BEST + 128 * 8;

__global__ __launch_bounds__(256) void biggemm_mma(
    int cb,
    const float* __restrict__ b_fc,
    const float* __restrict__ gum,
    float* __restrict__ out,
    int t)
{
    extern __shared__ __align__(16) char dsm[];
    const uint32_t smb = smem_u32(dsm);
    const int tid = threadIdx.x;
    const int wid = tid >> 5, lane = tid & 31;
    const int warpM = wid & 1, warpN = wid >> 1;
    const int ntile = blockIdx.x;
    const int nbase = ntile * 128;

    const __nv_bfloat16* Ah = g_hhi[cb][NL_ - 1];
    const __nv_bfloat16* Al = g_hlo[cb][NL_ - 1];

    unsigned long long* sbest = (unsigned long long*)(dsm + SM_BEST);
    if (tid < 128) sbest[tid] = 0ULL;

    const int aRow = warpM * 64 + (lane & 7) + ((lane >> 3) & 1) * 8;
    const int aK   = ((lane >> 4) & 1) * 8;
    const uint32_t aBase = smb + (uint32_t)(aRow * LDA + aK) * 2;
    const int bl   = lane & 15;
    const int bRow = warpN * 32 + (bl & 7);
    const int bK   = ((bl >> 3) & 1) * 8;
    const uint32_t bBase = smb + 2 * ARRB + (uint32_t)(bRow * LDA + bK) * 2;

    const size_t wtile = ((size_t)ntile * KC) << 12;

    auto load_stage = [&](int stage, int kc) {
        const uint32_t sdst = smb + stage * STG;
        #pragma unroll
        for (int i = 0; i < 8; i++) {
            int c = tid + i * 256;
            int arr = c >> 9, idx = c & 511;
            int row = idx >> 2, seg = idx & 3;
            uint32_t dst = sdst + arr * ARRB + (uint32_t)(row * LDA + seg * 8) * 2;
            const __nv_bfloat16* src;
            if (arr == 0)      src = Ah + row * H_ + kc * 32 + seg * 8;
            else if (arr == 1) src = Al + row * H_ + kc * 32 + seg * 8;
            else if (arr == 2) src = g_Whi + wtile + ((size_t)kc * 128 + row) * 32 + seg * 8;
            else               src = g_Wlo + wtile + ((size_t)kc * 128 + row) * 32 + seg * 8;
            CPA16(dst, src);
        }
    };

    float acc[4][4][4];
    #pragma unroll
    for (int mf = 0; mf < 4; mf++)
        #pragma unroll
        for (int nf = 0; nf < 4; nf++)
            #pragma unroll
            for (int i = 0; i < 4; i++) acc[mf][nf][i] = 0.0f;

    load_stage(0, 0);
    CPA_COMMIT();

    for (int kc = 0; kc < KC; kc++) {
        if (kc + 1 < KC) {
            load_stage((kc + 1) & 1, kc + 1);
            CPA_COMMIT();
            CPA_WAIT(1);
        } else {
            CPA_WAIT(0);
        }
        __syncthreads();

        const uint32_t soff = (kc & 1) * STG;
        #pragma unroll
        for (int k16 = 0; k16 < 2; k16++) {
            const uint32_t kb2 = (uint32_t)(k16 * 16) * 2;
            uint32_t bhi[4][2], blo[4][2];
            #pragma unroll
            for (int nf = 0; nf < 4; nf++) {
                uint32_t ba = bBase + soff + (uint32_t)(nf * 8 * LDA) * 2 + kb2;
                ldsm2(bhi[nf], ba);
                ldsm2(blo[nf], ba + ARRB);
            }
            uint32_t ahi[4][4], alo[4][4];
            #pragma unroll
            for (int mf = 0; mf < 4; mf++) {
                uint32_t aa = aBase + soff + (uint32_t)(mf * 16 * LDA) * 2 + kb2;
                ldsm4(ahi[mf], aa);
                ldsm4(alo[mf], aa + ARRB);
            }
            #pragma unroll
            for (int mf = 0; mf < 4; mf++)
                #pragma unroll
                for (int nf = 0; nf < 4; nf++) {
                    mma16816(acc[mf][nf], ahi[mf], bhi[nf]);
                    mma16816(acc[mf][nf], ahi[mf], blo[nf]);
                    mma16816(acc[mf][nf], alo[mf], bhi[nf]);
                }
        }
        __syncthreads();
    }

    const int tq = lane & 3, gid = lane >> 2;
    float2 bz[4];
    #pragma unroll
    for (int nf = 0; nf < 4; nf++)
        bz[nf] = *(const float2*)&b_fc[nbase + warpN * 32 + nf * 8 + 2 * tq];

    #pragma unroll
    for (int mf = 0; mf < 4; mf++) {
        #pragma unroll
        for (int half = 0; half < 2; half++) {
            const int r = warpM * 64 + mf * 16 + gid + half * 8;
            unsigned long long bk = 0ULL;
            #pragma unroll
            for (int nf = 0; nf < 4; nf++) {
                const int col = nbase + warpN * 32 + nf * 8 + 2 * tq;
                float v0 = acc[mf][nf][half * 2 + 0] + bz[nf].x;
                float v1 = acc[mf][nf][half * 2 + 1] + bz[nf].y;
                if (out) *(float2*)&out[((size_t)r * S_ + t) * V_ + col] = make_float2(v0, v1);
                float2 g = *(const float2*)&gum[(size_t)r * V_ + col];
                unsigned long long k0 = ((unsigned long long)fkey(v0 + g.x) << 32) | (unsigned)col;
                unsigned long long k1 = ((unsigned long long)fkey(v1 + g.y) << 32) | (unsigned)(col + 1);
                if (k0 > bk) bk = k0;
                if (k1 > bk) bk = k1;
            }
            #pragma unroll
            for (int m = 2; m >= 1; m >>= 1) {
                unsigned long long o = __shfl_xor_sync(0xffffffffu, bk, m);
                if (o > bk) bk = o;
            }
            if (tq == 0) atomicMax(&sbest[r], bk);
        }
    }
    __syncthreads();
    if (tid < 128) atomicMax(&g_arg[tid], sbest[tid]);
}

// ---------------- finalize: token feedback + samples + x0 = split(emb[tok]) ----------------
__global__ void finalize_kernel(int t, float* __restrict__ samples_out,
                                const float* __restrict__ emb) {
    const int b = blockIdx.x;
    __shared__ int stok;
    if (threadIdx.x == 0) {
        int idx;
        if (t >= 0) {
            unsigned long long k = g_arg[b];
            idx = (int)(unsigned)(k & 0xffffffffu);
            g_tok[b] = idx;
            g_arg[b] = 0ULL;
            if (samples_out) samples_out[(size_t)b * S_ + t] = (float)idx;
        } else {
            idx = g_tok[b];
        }
        stok = idx;
    }
    __syncthreads();
    const float* er = emb + (size_t)stok * E_;
    for (int j = threadIdx.x; j < E_; j += blockDim.x) {
        float x = er[j];
        __nv_bfloat16 hv = __float2bfloat16(x);
        g_x0hi[b * E_ + j] = hv;
        g_x0lo[b * E_ + j] = __float2bfloat16(x - __bfloat162float(hv));
    }
}

// ---------------- launch ----------------
extern "C" void kernel_launch(void* const* d_in, const int* in_sizes, int n_in,
                              void* d_out, int out_size) {
    const float* noise = (const float*)d_in[0];
    const float* emb   = (const float*)d_in[1];
    const float* W_lat = (const float*)d_in[2];
    const float* b_lat = (const float*)d_in[3];
    const float* W_ih0 = (const float*)d_in[4];
    const float* W_hh0 = (const float*)d_in[5];
    const float* b_ih0 = (const float*)d_in[6];
    const float* b_hh0 = (const float*)d_in[7];
    const float* W_ihr = (const float*)d_in[8];
    const float* W_hhr = (const float*)d_in[9];
    const float* b_ihr = (const float*)d_in[10];
    const float* b_hhr = (const float*)d_in[11];
    const float* W_fc  = (const float*)d_in[12];
    const float* b_fc  = (const float*)d_in[13];
    const float* gum   = (const float*)d_in[14];
    float* out = (float*)d_out;

    const long LOGN = (long)B_ * S_ * V_;
    float* logits_out  = ((long)out_size >= LOGN) ? out : nullptr;
    float* samples_out = ((long)out_size >= LOGN + (long)B_ * S_) ? out + LOGN : nullptr;
    if ((long)out_size == (long)B_ * S_) samples_out = out;

    cudaFuncSetAttribute(biggemm_mma, cudaFuncAttributeMaxDynamicSharedMemorySize, SM_TOTAL);
    cudaFuncSetAttribute(cell_mma, cudaFuncAttributeMaxDynamicSharedMemorySize, CSM_TOTAL);

    init_kernel<<<(NL_ * BH_ + 255) / 256, 256>>>(noise, W_lat, b_lat);
    convw_kernel<<<(V_ * H_ + 255) / 256, 256>>>(W_fc);
    convcell_kernel<<<(2048 * (E_ + H_) + 255) / 256, 256>>>(0, E_, W_ih0, W_hh0);
    convcell_kernel<<<(2048 * (2 * H_) + 255) / 256, 256>>>(1, H_, W_ihr, W_hhr);
    convcell_kernel<<<(2048 * (2 * H_) + 255) / 256, 256>>>(2, H_,
                                                            W_ihr + (size_t)4 * H_ * H_,
                                                            W_hhr + (size_t)4 * H_ * H_);
    finalize_kernel<<<B_, 128>>>(-1, nullptr, emb);  // x0 from start token

    for (int t = 0; t < S_; t++) {
        const int cbi = t & 1, pbi = cbi ^ 1;
        dim3 cgrid(32, 2);   // 64 CTAs per cell
        cell_mma<<<cgrid, 128, CSM_TOTAL>>>(cbi, pbi, 0, E_, b_ih0, b_hh0);
        cell_mma<<<cgrid, 128, CSM_TOTAL>>>(cbi, pbi, 1, H_, b_ihr, b_hhr);
        cell_mma<<<cgrid, 128, CSM_TOTAL>>>(cbi, pbi, 2, H_,
                                            b_ihr + 4 * H_, b_hhr + 4 * H_);
        biggemm_mma<<<NTILE, 256, SM_TOTAL>>>(cbi, b_fc, gum + (size_t)t * B_ * V_,
                                              logits_out, t);
        finalize_kernel<<<B_, 128>>>(t, samples_out, emb);
    }
}